// round 10
// baseline (speedup 1.0000x reference)
#include <cuda_runtime.h>

// Problem constants (fixed by the reference)
#define NROWS 8192
#define MM    128
#define DZ    128
#define DX    128
#define HH    4

// xWb[m] = x[:,m] @ W[DZ:, :] + b   (2 KB, precomputed once per launch)
__device__ float4 g_xWb[MM];

// ---------------------------------------------------------------------------
// Kernel 1: xWb. One block, 1024 threads: thread = (m, octant q), each
// sums 16 d's; combine 8 partials via shared; first 128 threads store.
// ---------------------------------------------------------------------------
__global__ __launch_bounds__(1024)
void xwb_kernel(const float* __restrict__ x,
                const float* __restrict__ W,
                const float* __restrict__ b) {
    __shared__ float4 s_part[8][MM];
    const float4* __restrict__ W4 = reinterpret_cast<const float4*>(W);

    int m = threadIdx.x & (MM - 1);
    int q = threadIdx.x >> 7;            // 0..7
    float a0 = 0.f, a1 = 0.f, a2 = 0.f, a3 = 0.f;
#pragma unroll
    for (int j = 0; j < 16; j++) {
        int d = q * 16 + j;
        float xv = x[d * MM + m];
        float4 w = W4[DZ + d];
        a0 = fmaf(xv, w.x, a0);
        a1 = fmaf(xv, w.y, a1);
        a2 = fmaf(xv, w.z, a2);
        a3 = fmaf(xv, w.w, a3);
    }
    s_part[q][m] = make_float4(a0, a1, a2, a3);
    __syncthreads();

    if (threadIdx.x < MM) {
        float4 bb = *reinterpret_cast<const float4*>(b);
        float s0 = bb.x, s1 = bb.y, s2 = bb.z, s3 = bb.w;
#pragma unroll
        for (int qq = 0; qq < 8; qq++) {
            float4 p = s_part[qq][threadIdx.x];
            s0 += p.x; s1 += p.y; s2 += p.z; s3 += p.w;
        }
        g_xWb[threadIdx.x] = make_float4(s0, s1, s2, s3);
    }
}

// ---------------------------------------------------------------------------
// Kernel 2: warp-autonomous. One warp per row n. No smem, no barriers.
//  - lane loads z[n, 4*lane..4*lane+3] (one LDG.128, coalesced)
//  - 4 W float4 loads (L1-hot after first warp)
//  - xor-butterfly reduce -> full sum in ALL lanes
//  - lane writes out[n, lane+32k, :] for k=0..3 (4 coalesced STG.128)
// ---------------------------------------------------------------------------
#define K2_THREADS 256
#define WARPS_PER_BLK (K2_THREADS / 32)          // 8
#define K2_BLOCKS (NROWS / WARPS_PER_BLK)        // 1024

__global__ __launch_bounds__(K2_THREADS)
void row_kernel(const float* __restrict__ z,
                const float* __restrict__ W,
                float* __restrict__ out) {
    const int lane = threadIdx.x & 31;
    const int warp = threadIdx.x >> 5;
    const int n = blockIdx.x * WARPS_PER_BLK + warp;

    const float4* __restrict__ W4 = reinterpret_cast<const float4*>(W);

    // Independent loads first (z from DRAM/L2, W + xWb from L1 after warm-up)
    float4 zv = reinterpret_cast<const float4*>(z + (size_t)n * DZ)[lane];
    float4 w0 = W4[4 * lane + 0];
    float4 w1 = W4[4 * lane + 1];
    float4 w2 = W4[4 * lane + 2];
    float4 w3 = W4[4 * lane + 3];
    float4 xw0 = g_xWb[lane];
    float4 xw1 = g_xWb[lane + 32];
    float4 xw2 = g_xWb[lane + 64];
    float4 xw3 = g_xWb[lane + 96];

    float a0 = zv.x * w0.x + zv.y * w1.x + zv.z * w2.x + zv.w * w3.x;
    float a1 = zv.x * w0.y + zv.y * w1.y + zv.z * w2.y + zv.w * w3.y;
    float a2 = zv.x * w0.z + zv.y * w1.z + zv.z * w2.z + zv.w * w3.z;
    float a3 = zv.x * w0.w + zv.y * w1.w + zv.z * w2.w + zv.w * w3.w;

#pragma unroll
    for (int off = 16; off > 0; off >>= 1) {
        a0 += __shfl_xor_sync(0xffffffffu, a0, off);
        a1 += __shfl_xor_sync(0xffffffffu, a1, off);
        a2 += __shfl_xor_sync(0xffffffffu, a2, off);
        a3 += __shfl_xor_sync(0xffffffffu, a3, off);
    }
    // Butterfly leaves the full row sum (a0..a3) in every lane.

    float4* __restrict__ out4 = reinterpret_cast<float4*>(out) + (size_t)n * MM;
    float4 o;
    o.x = fmaxf(a0 + xw0.x, 0.f); o.y = fmaxf(a1 + xw0.y, 0.f);
    o.z = fmaxf(a2 + xw0.z, 0.f); o.w = fmaxf(a3 + xw0.w, 0.f);
    out4[lane] = o;
    o.x = fmaxf(a0 + xw1.x, 0.f); o.y = fmaxf(a1 + xw1.y, 0.f);
    o.z = fmaxf(a2 + xw1.z, 0.f); o.w = fmaxf(a3 + xw1.w, 0.f);
    out4[lane + 32] = o;
    o.x = fmaxf(a0 + xw2.x, 0.f); o.y = fmaxf(a1 + xw2.y, 0.f);
    o.z = fmaxf(a2 + xw2.z, 0.f); o.w = fmaxf(a3 + xw2.w, 0.f);
    out4[lane + 64] = o;
    o.x = fmaxf(a0 + xw3.x, 0.f); o.y = fmaxf(a1 + xw3.y, 0.f);
    o.z = fmaxf(a2 + xw3.z, 0.f); o.w = fmaxf(a3 + xw3.w, 0.f);
    out4[lane + 96] = o;
}

// ---------------------------------------------------------------------------
// Launch. Inputs (metadata order): z [N*DZ], x [DX*M], W [(DZ+DX)*H], b [H].
// Output: float32 [N*M*H].
// ---------------------------------------------------------------------------
extern "C" void kernel_launch(void* const* d_in, const int* in_sizes, int n_in,
                              void* d_out, int out_size) {
    const float* z = (const float*)d_in[0];
    const float* x = (const float*)d_in[1];
    const float* W = (const float*)d_in[2];
    const float* b = (const float*)d_in[3];
    float* out = (float*)d_out;

    xwb_kernel<<<1, 1024>>>(x, W, b);
    row_kernel<<<K2_BLOCKS, K2_THREADS>>>(z, W, out);
}